// round 4
// baseline (speedup 1.0000x reference)
#include <cuda_runtime.h>

// InpatientInterventions: out[t,g] = sum over events e active at t0[t]
// (start<=t0<end) of rate[e]*weights[index[e]], grouped by group_id[index[e]].
// Strategy: per-event difference array over the (sorted) t0 axis + columnwise
// hierarchical prefix scan.

#define TC 128            // rows per scan chunk
#define MAX_PART (64 * 4096)

__device__ float g_partials[MAX_PART];   // [nchunk, G] chunk sums

// --- Kernel 1: per-event scatter of +c at t_lo, -c at t_hi -------------------
__global__ void scatter_diff(const int* __restrict__ index,
                             const float* __restrict__ rate,
                             const float* __restrict__ start,
                             const float* __restrict__ endt,
                             const float* __restrict__ t0,
                             const int* __restrict__ group_id,
                             const float* __restrict__ weights,
                             float* __restrict__ out,
                             int E, int T, int G)
{
    int e = blockIdx.x * blockDim.x + threadIdx.x;
    if (e >= E) return;

    float s  = start[e];
    float en = endt[e];

    // lower_bound: first t with t0[t] >= s
    int lo = 0, hi = T;
    while (lo < hi) {
        int mid = (lo + hi) >> 1;
        if (__ldg(&t0[mid]) < s) lo = mid + 1; else hi = mid;
    }
    int t_lo = lo;
    if (t_lo >= T) return;            // never becomes active in horizon

    // lower_bound: first t with t0[t] >= en  (search only [t_lo, T))
    hi = T;                            // lo already == t_lo
    while (lo < hi) {
        int mid = (lo + hi) >> 1;
        if (__ldg(&t0[mid]) < en) lo = mid + 1; else hi = mid;
    }
    int t_hi = lo;
    if (t_hi <= t_lo) return;          // empty active range

    int   src = __ldg(&index[e]);
    float c   = rate[e] * __ldg(&weights[src]);
    int   g   = __ldg(&group_id[src]);

    atomicAdd(&out[(size_t)t_lo * G + g], c);
    if (t_hi < T)
        atomicAdd(&out[(size_t)t_hi * G + g], -c);
}

// --- Kernel 2: per-(chunk, column) sums -------------------------------------
__global__ void chunk_sums(const float* __restrict__ out, int T, int G)
{
    int g = blockIdx.x * blockDim.x + threadIdx.x;
    if (g >= G) return;
    int c  = blockIdx.y;
    int r0 = c * TC;
    int r1 = min(r0 + TC, T);
    float acc = 0.f;
    #pragma unroll 4
    for (int r = r0; r < r1; ++r)
        acc += out[(size_t)r * G + g];
    g_partials[c * G + g] = acc;
}

// --- Kernel 3: scan each chunk, seeded with exclusive sum of prior chunks ----
__global__ void scan_chunks(float* __restrict__ out, int T, int G)
{
    int g = blockIdx.x * blockDim.x + threadIdx.x;
    if (g >= G) return;
    int c = blockIdx.y;

    float acc = 0.f;
    for (int cc = 0; cc < c; ++cc)        // <=63 coalesced L2-hot loads
        acc += g_partials[cc * G + g];

    int r0 = c * TC;
    int r1 = min(r0 + TC, T);
    for (int r = r0; r < r1; ++r) {
        acc += out[(size_t)r * G + g];
        out[(size_t)r * G + g] = acc;
    }
}

extern "C" void kernel_launch(void* const* d_in, const int* in_sizes, int n_in,
                              void* d_out, int out_size)
{
    const int*   index    = (const int*)  d_in[0];
    const float* rate     = (const float*)d_in[1];
    const float* start    = (const float*)d_in[2];
    const float* endt     = (const float*)d_in[3];
    const float* t0       = (const float*)d_in[4];
    const int*   group_id = (const int*)  d_in[5];
    const float* weights  = (const float*)d_in[6];
    float*       out      = (float*)d_out;

    int E = in_sizes[0];
    int T = in_sizes[4];
    int G = out_size / T;                 // 1024 for this problem

    cudaMemsetAsync(out, 0, (size_t)out_size * sizeof(float));

    int nchunk = (T + TC - 1) / TC;       // 32 for T=4096

    scatter_diff<<<(E + 255) / 256, 256>>>(index, rate, start, endt, t0,
                                           group_id, weights, out, E, T, G);

    dim3 grid((G + 255) / 256, nchunk);
    chunk_sums<<<grid, 256>>>(out, T, G);
    scan_chunks<<<grid, 256>>>(out, T, G);
}

// round 5
// speedup vs baseline: 1.6997x; 1.6997x over previous
#include <cuda_runtime.h>

// InpatientInterventions on GB300.
// out[t,g] = sum_e rate[e]*weights[index[e]] * [start<=t0[t]<end], g=group_id[index[e]]
// t0 sorted -> each event is a constant over a contiguous t-range.
// Sparse difference-endpoint pipeline: endpoints bucketed per 128-row chunk,
// chunk bases via tiny chunk-level scan, output written exactly once
// (write-only 16MB) by a smem-tile prefix-scan writer.

#define TC        128          // rows per chunk
#define CBLK      256          // columns per writer block (== writer blockDim)
#define NCHUNK_MAX 64
#define CAP       32768        // endpoint capacity per chunk (>= 2*E total)
#define CNT_PAD   64           // pad counters to 256B to keep them on distinct L2 slices

__device__ unsigned int g_cnt[NCHUNK_MAX * CNT_PAD];
__device__ uint2        g_ep[NCHUNK_MAX * CAP];       // .x = (row<<11)|g, .y = float bits
__device__ float        g_cdiff[NCHUNK_MAX * 2048];   // [chunk][G] sums -> exclusive bases

// ---------------------------------------------------------------- zero scratch
__global__ void zero_scratch(int nchunk, int G)
{
    int i = blockIdx.x * blockDim.x + threadIdx.x;
    int stride = gridDim.x * blockDim.x;
    for (int j = i; j < NCHUNK_MAX * CNT_PAD; j += stride) g_cnt[j] = 0u;
    int n = nchunk * G;
    for (int j = i; j < n; j += stride) g_cdiff[j] = 0.f;
}

// ------------------------------------------------- per-event endpoint scatter
// Binary searches run against t0 staged in shared memory (T*4 bytes dyn smem).
__global__ void scatter_ep(const int*   __restrict__ index,
                           const float* __restrict__ rate,
                           const float* __restrict__ start,
                           const float* __restrict__ endt,
                           const float* __restrict__ t0,
                           const int*   __restrict__ group_id,
                           const float* __restrict__ weights,
                           int E, int T, int G)
{
    extern __shared__ float s_t0[];
    for (int i = threadIdx.x; i < T; i += blockDim.x)
        s_t0[i] = t0[i];
    __syncthreads();

    int e = blockIdx.x * blockDim.x + threadIdx.x;
    if (e >= E) return;

    float s  = start[e];
    float en = endt[e];

    // lower_bound(t0, s)
    int lo = 0, hi = T;
    while (lo < hi) { int m = (lo + hi) >> 1; if (s_t0[m] < s) lo = m + 1; else hi = m; }
    int t_lo = lo;
    if (t_lo >= T) return;

    // lower_bound(t0, en) over [t_lo, T)
    hi = T;
    while (lo < hi) { int m = (lo + hi) >> 1; if (s_t0[m] < en) lo = m + 1; else hi = m; }
    int t_hi = lo;
    if (t_hi <= t_lo) return;

    int   src = __ldg(&index[e]);
    float c   = rate[e] * __ldg(&weights[src]);
    int   g   = __ldg(&group_id[src]);

    { // +c endpoint at t_lo
        int ch = t_lo / TC, r = t_lo - ch * TC;
        unsigned p = atomicAdd(&g_cnt[ch * CNT_PAD], 1u);
        g_ep[ch * CAP + p] = make_uint2((unsigned)((r << 11) | g), __float_as_uint(c));
        atomicAdd(&g_cdiff[ch * G + g], c);
    }
    if (t_hi < T) { // -c endpoint at t_hi
        int ch = t_hi / TC, r = t_hi - ch * TC;
        unsigned p = atomicAdd(&g_cnt[ch * CNT_PAD], 1u);
        g_ep[ch * CAP + p] = make_uint2((unsigned)((r << 11) | g), __float_as_uint(-c));
        atomicAdd(&g_cdiff[ch * G + g], -c);
    }
}

// ------------------------------------ exclusive scan of chunk sums per column
__global__ void chunk_scan(int nchunk, int G)
{
    int g = blockIdx.x * blockDim.x + threadIdx.x;
    if (g >= G) return;
    float acc = 0.f;
    for (int c = 0; c < nchunk; ++c) {
        float v = g_cdiff[c * G + g];
        g_cdiff[c * G + g] = acc;      // becomes exclusive base of chunk c
        acc += v;
    }
}

// ------------------------------------------------- write-only output producer
// Block = (chunk ch) x (columns [g0, g0+CBLK)). Dyn smem tile TC*CBLK floats.
__global__ void writer(float* __restrict__ out, int T, int G)
{
    extern __shared__ float tile[];            // [TC][CBLK]
    int ch = blockIdx.y;
    int g0 = blockIdx.x * CBLK;

    // zero the tile (vectorized)
    float4* t4 = (float4*)tile;
    int nw4 = (TC * CBLK) / 4;
    for (int i = threadIdx.x; i < nw4; i += blockDim.x)
        t4[i] = make_float4(0.f, 0.f, 0.f, 0.f);
    __syncthreads();

    // apply this chunk's endpoints that land in our column window
    unsigned cnt = g_cnt[ch * CNT_PAD];
    const uint2* ep = &g_ep[ch * CAP];
    for (unsigned i = threadIdx.x; i < cnt; i += blockDim.x) {
        uint2 kv = ep[i];
        int g  = (int)(kv.x & 2047u);
        int r  = (int)(kv.x >> 11);
        int gl = g - g0;
        if ((unsigned)gl < (unsigned)CBLK)
            atomicAdd(&tile[r * CBLK + gl], __uint_as_float(kv.y));
    }
    __syncthreads();

    // per-column prefix scan, coalesced streaming store
    int g = g0 + threadIdx.x;
    if (g >= G) return;
    float acc = g_cdiff[ch * G + g];
    int r0   = ch * TC;
    int rend = min(TC, T - r0);
    for (int r = 0; r < rend; ++r) {
        acc += tile[r * CBLK + threadIdx.x];
        out[(size_t)(r0 + r) * G + g] = acc;
    }
}

// -----------------------------------------------------------------------------
extern "C" void kernel_launch(void* const* d_in, const int* in_sizes, int n_in,
                              void* d_out, int out_size)
{
    const int*   index    = (const int*)  d_in[0];
    const float* rate     = (const float*)d_in[1];
    const float* start    = (const float*)d_in[2];
    const float* endt     = (const float*)d_in[3];
    const float* t0       = (const float*)d_in[4];
    const int*   group_id = (const int*)  d_in[5];
    const float* weights  = (const float*)d_in[6];
    float*       out      = (float*)d_out;

    int E = in_sizes[0];
    int T = in_sizes[4];
    int G = out_size / T;                      // 1024

    int nchunk = (T + TC - 1) / TC;            // 32 for T=4096

    // writer needs 128KB dynamic smem (> default 48KB)
    static_assert(TC * CBLK * sizeof(float) == 131072, "tile size");
    cudaFuncSetAttribute(writer, cudaFuncAttributeMaxDynamicSharedMemorySize,
                         TC * CBLK * (int)sizeof(float));

    zero_scratch<<<64, 256>>>(nchunk, G);

    scatter_ep<<<(E + 127) / 128, 128, T * sizeof(float)>>>(
        index, rate, start, endt, t0, group_id, weights, E, T, G);

    chunk_scan<<<(G + 255) / 256, 256>>>(nchunk, G);

    dim3 wgrid((G + CBLK - 1) / CBLK, nchunk);
    writer<<<wgrid, CBLK, TC * CBLK * sizeof(float)>>>(out, T, G);
}